// round 16
// baseline (speedup 1.0000x reference)
#include <cuda_runtime.h>
#include <cuda_bf16.h>
#include <cstdint>

// ---------------- problem constants (fixed shapes) ----------------
constexpr int cL  = 8192;   // tokens
constexpr int cE  = 512;    // embed = d
constexpr int cD  = 512;
constexpr int cNG = 16;     // graphs

// ---------------- scratch (device globals; no allocs allowed) ------
__device__ float g_XZ   [cL * 2 * cD];        // 32 MB  [x_in | z]
__device__ float g_XC   [cL * cD];            // 16 MB  silu(conv)
__device__ float g_DBC  [cL * 64];            //  2 MB  [dt(32) | B(16) | C(16)]
__device__ float g_DELTA[cL * cD];            // 16 MB
__device__ int   g_seg_start[cNG];
__device__ int   g_seg_end  [cNG];

// bf16 split A-operand buffers (planar hi/lo)
__device__ __nv_bfloat16 g_INhi[cL * 3 * cE];   // concat(q,kv,ke)
__device__ __nv_bfloat16 g_INlo[cL * 3 * cE];
__device__ __nv_bfloat16 g_Xhi [cL * cE];       // GEMM1 out (leaky)
__device__ __nv_bfloat16 g_Xlo [cL * cE];
__device__ __nv_bfloat16 g_Yhi [cL * cD];       // scan out
__device__ __nv_bfloat16 g_Ylo [cL * cD];
// weights: hi/lo interleaved per 2-k group: [hi(k),hi(k+1),lo(k),lo(k+1)]
__device__ __nv_bfloat16 g_WWi[cE * 2 * (3 * cE)];     // 512 x 3072
__device__ __nv_bfloat16 g_WIi[(2 * cD) * 2 * cE];     // 1024 x 1024
__device__ __nv_bfloat16 g_WOi[cE * 2 * cD];           // 512 x 1024

// ---------------- helpers ------------------------------------------
__device__ __forceinline__ uint32_t smem_u32(const void* p) {
    uint32_t a;
    asm("{ .reg .u64 t; cvta.to.shared.u64 t, %1; cvt.u32.u64 %0, t; }"
        : "=r"(a) : "l"(p));
    return a;
}
__device__ __forceinline__ void ldsm4(uint32_t* r, uint32_t addr) {
    asm volatile("ldmatrix.sync.aligned.m8n8.x4.shared.b16 {%0,%1,%2,%3}, [%4];"
                 : "=r"(r[0]), "=r"(r[1]), "=r"(r[2]), "=r"(r[3]) : "r"(addr));
}
__device__ __forceinline__ void mma16816(float* c, const uint32_t* a, const uint32_t* b) {
    asm volatile("mma.sync.aligned.m16n8k16.row.col.f32.bf16.bf16.f32 "
                 "{%0,%1,%2,%3}, {%4,%5,%6,%7}, {%8,%9}, {%0,%1,%2,%3};"
                 : "+f"(c[0]), "+f"(c[1]), "+f"(c[2]), "+f"(c[3])
                 : "r"(a[0]), "r"(a[1]), "r"(a[2]), "r"(a[3]), "r"(b[0]), "r"(b[1]));
}
__device__ __forceinline__ void cp16(uint32_t dst, const void* src) {
    asm volatile("cp.async.cg.shared.global [%0], [%1], 16;"
                 :: "r"(dst), "l"(src) : "memory");
}
__device__ __forceinline__ void cp_commit() {
    asm volatile("cp.async.commit_group;" ::: "memory");
}
template<int N>
__device__ __forceinline__ void cp_wait() {
    asm volatile("cp.async.wait_group %0;" :: "n"(N) : "memory");
}
// split one fp32 into bf16 hi + bf16 lo
__device__ __forceinline__ void split1(float v, __nv_bfloat16& h, __nv_bfloat16& l) {
    h = __float2bfloat16_rn(v);
    l = __float2bfloat16_rn(v - __bfloat162float(h));
}
__device__ __forceinline__ void split4(float4 v, uint2& h, uint2& l) {
    __nv_bfloat16 h0, h1, h2, h3, l0, l1, l2, l3;
    split1(v.x, h0, l0); split1(v.y, h1, l1);
    split1(v.z, h2, l2); split1(v.w, h3, l3);
    __nv_bfloat162 H01{h0, h1}, H23{h2, h3}, L01{l0, l1}, L23{l2, l3};
    h.x = *(uint32_t*)&H01; h.y = *(uint32_t*)&H23;
    l.x = *(uint32_t*)&L01; l.y = *(uint32_t*)&L23;
}

// ---------------- packed fp32x2 (small GEMM) -----------------------
__device__ __forceinline__ unsigned long long pk2(float lo, float hi) {
    unsigned long long r;
    asm("mov.b64 %0, {%1, %2};" : "=l"(r) : "f"(lo), "f"(hi));
    return r;
}
__device__ __forceinline__ void fma2(unsigned long long& d,
                                     unsigned long long a, unsigned long long b) {
    asm("fma.rn.f32x2 %0, %1, %2, %0;" : "+l"(d) : "l"(a), "l"(b));
}
__device__ __forceinline__ void upk2(unsigned long long v, float& lo, float& hi) {
    asm("mov.b64 {%0, %1}, %2;" : "=f"(lo), "=f"(hi) : "l"(v));
}

// ---------------- conversion prepasses -----------------------------
__global__ __launch_bounds__(256)
void cvt_inputs(const float* __restrict__ q, const float* __restrict__ kv,
                const float* __restrict__ ke)
{
    int i = blockIdx.x * 256 + threadIdx.x;       // one per 4 elems
    int e = i * 4;
    int row = e / 1536;
    int col = e - row * 1536;
    const float* base = (col < 512) ? q : ((col < 1024) ? kv : ke);
    float4 v = *(const float4*)(base + (size_t)row * 512 + (col & 511));
    uint2 h, l;
    split4(v, h, l);
    *(uint2*)(g_INhi + e) = h;
    *(uint2*)(g_INlo + e) = l;
}

// weights -> hi/lo interleaved per 2-k group
__global__ __launch_bounds__(256)
void cvt_w_i(const float* __restrict__ src, __nv_bfloat16* __restrict__ dst, int K)
{
    int e = (blockIdx.x * 256 + threadIdx.x) * 4;   // k multiple of 4
    int n = e / K;
    int k = e - n * K;
    float4 v = *(const float4*)(src + e);
    uint2 h, l;
    split4(v, h, l);
    uint4 o = make_uint4(h.x, l.x, h.y, l.y);
    *(uint4*)(dst + (size_t)n * 2 * K + 2 * k) = o;
}

// ---------------- segment boundary extraction ----------------------
__global__ void seg_mark(const int* __restrict__ eb) {
    int tid = threadIdx.x;
    if (tid < cNG) { g_seg_start[tid] = -1; g_seg_end[tid] = -1; }
    __syncthreads();
    for (int t = tid; t < cL; t += blockDim.x) {
        int g = eb[t];
        if (t == 0      || eb[t - 1] != g) g_seg_start[g] = t;
        if (t == cL - 1 || eb[t + 1] != g) g_seg_end[g]   = t + 1;
    }
}

// =====================================================================
// HMMA split-bf16 NT GEMM, A via cp.async smem (2-stage), B via direct
// LDG.64 register fragments from interleaved weights (L2-resident).
// C = A*B^T ; terms hi*hi + hi*lo + lo*hi, fp32 accumulate.
// Tile 128x128, BK=32. 8 warps of 64x32.
// MODE 0: bias + leaky -> bf16 hi/lo out ; MODE 1: fp32 store ;
// MODE 2: atomicAdd into C[idx[row]*N + col]
// =====================================================================
constexpr int TSTR = 40;                 // smem row stride (bf16 elems)
constexpr int TSZ  = 128 * TSTR;         // one tile (5120 elems, 10 KB)
constexpr int MG_SMEM = 2 * 2 * TSZ * 2; // 2 stages x (AH|AL) = 40960 B

template<int MODE>
__global__ __launch_bounds__(256, 2)
void mma_gemm(const __nv_bfloat16* __restrict__ Ahi, const __nv_bfloat16* __restrict__ Alo,
              const __nv_bfloat16* __restrict__ Bi,
              const float* __restrict__ bias, float* __restrict__ C,
              __nv_bfloat16* __restrict__ Ohi, __nv_bfloat16* __restrict__ Olo,
              const int* __restrict__ idx, int K, int N)
{
    extern __shared__ __nv_bfloat16 smd[];
    const int tid  = threadIdx.x;
    const int wid  = tid >> 5;
    const int lane = tid & 31;
    const int wm   = wid & 1;                 // 2 warp-rows (64 each)
    const int wn   = wid >> 1;                // 4 warp-cols (32 each)
    const int bm   = blockIdx.y * 128;
    const int bn   = blockIdx.x * 128;

    float acc[4][4][4];
#pragma unroll
    for (int i = 0; i < 4; i++)
#pragma unroll
        for (int j = 0; j < 4; j++)
#pragma unroll
            for (int k = 0; k < 4; k++) acc[i][j][k] = 0.f;

    const uint32_t sb = smem_u32(smd);
    const int KT = K / 32;

    const __nv_bfloat16* Abase[2] = { Ahi + (size_t)bm * K, Alo + (size_t)bm * K };

    auto issue = [&](int c) {
        const int st = c & 1;
        const int kb = c * 32;
#pragma unroll
        for (int i = 0; i < 4; i++) {
            int g  = tid + 256 * i;        // 0..1023
            int t  = g >> 9;               // AH / AL
            int gg = g & 511;
            int row = gg >> 2, u = gg & 3;
            uint32_t dst = sb + 2 * (st * 2 * TSZ + t * TSZ + row * TSTR + u * 8);
            cp16(dst, Abase[t] + (size_t)row * K + kb + u * 8);
        }
        cp_commit();
    };

    // B fragment base: lane n-row and k-phase (PTX m16n8k16 B mapping)
    const int nb = bn + wn * 32 + (lane >> 2);
    const int t4 = (lane & 3);

    issue(0);

    for (int c = 0; c < KT; c++) {
        if (c + 1 < KT) issue(c + 1);

        // ---- B fragments via direct LDG.64 (hi+lo in one load) ----
        uint32_t bh[2][4][2], bl[2][4][2];
#pragma unroll
        for (int ks = 0; ks < 2; ks++) {
            const int kk = c * 32 + ks * 16 + 2 * t4;
#pragma unroll
            for (int nf = 0; nf < 4; nf++) {
                const __nv_bfloat16* bp =
                    Bi + (size_t)(nb + nf * 8) * (2 * K) + 2 * kk;
                uint2 p0 = *(const uint2*)bp;          // k..k+1 (hi|lo)
                uint2 p1 = *(const uint2*)(bp + 16);   // k+8..k+9
                bh[ks][nf][0] = p0.x; bl[ks][nf][0] = p0.y;
                bh[ks][nf][1] = p1.x; bl[ks][nf][1] = p1.y;
            }
        }

        if (c + 1 < KT) cp_wait<1>(); else cp_wait<0>();
        __syncthreads();

        const uint32_t stb = sb + 2 * ((c & 1) * 2 * TSZ);
#pragma unroll
        for (int ks = 0; ks < 2; ks++) {
            const uint32_t arow = wm * 64 + (lane & 15);
            const uint32_t acol = ks * 16 + (lane >> 4) * 8;
#pragma unroll
            for (int mf = 0; mf < 4; mf++) {
                uint32_t ah[4], al[4];
                uint32_t off = (arow + mf * 16) * TSTR + acol;
                ldsm4(ah, stb + 2 * off);
                ldsm4(al, stb + 2 * (TSZ + off));
#pragma unroll
                for (int nf = 0; nf < 4; nf++) {
                    mma16816(acc[mf][nf], ah, bh[ks][nf]);
                    mma16816(acc[mf][nf], ah, bl[ks][nf]);
                    mma16816(acc[mf][nf], al, bh[ks][nf]);
                }
            }
        }
        __syncthreads();
    }

    // ---------------- epilogue ----------------
    const int r  = lane >> 2;
    const int cp = (lane & 3) * 2;
#pragma unroll
    for (int mf = 0; mf < 4; mf++) {
#pragma unroll
        for (int half = 0; half < 2; half++) {
            const int m = bm + wm * 64 + mf * 16 + r + half * 8;
            int node = 0;
            if constexpr (MODE == 2) node = idx[m];
#pragma unroll
            for (int nf = 0; nf < 4; nf++) {
                const int n = bn + wn * 32 + nf * 8 + cp;
                float v0 = acc[mf][nf][half * 2 + 0];
                float v1 = acc[mf][nf][half * 2 + 1];
                if constexpr (MODE == 0) {
                    float2 bv = *(const float2*)(bias + n);
                    v0 += bv.x; v1 += bv.y;
                    v0 = (v0 >= 0.f) ? v0 : 0.01f * v0;
                    v1 = (v1 >= 0.f) ? v1 : 0.01f * v1;
                    __nv_bfloat16 h0, h1, l0, l1;
                    split1(v0, h0, l0); split1(v1, h1, l1);
                    __nv_bfloat162 H{h0, h1}, L{l0, l1};
                    *(__nv_bfloat162*)(Ohi + (size_t)m * N + n) = H;
                    *(__nv_bfloat162*)(Olo + (size_t)m * N + n) = L;
                } else if constexpr (MODE == 1) {
                    *(float2*)(C + (size_t)m * N + n) = make_float2(v0, v1);
                } else {
                    float* p = C + (size_t)node * N + n;
                    atomicAdd(p + 0, v0);
                    atomicAdd(p + 1, v1);
                }
            }
        }
    }
}

// ---------------- small FFMA2 NT GEMM (dbc, N=64) -------------------
template<int BM, int BN, int TM, int TN>
__global__ __launch_bounds__((BM / TM) * (BN / TN))
void gemm_nt_small(const float* __restrict__ A0, const float* __restrict__ Bm,
                   float* __restrict__ C, int K, int N)
{
    constexpr int THREADS = (BM / TM) * (BN / TN);
    constexpr int BK  = 16;
    constexpr int NLA = (BM * BK / 4) / THREADS;
    constexpr int NLB = (BN * BK / 4) / THREADS;
    constexpr int PAD = 4;
    constexpr int NCHM = TM / 4, NCHN = TN / 4;
    constexpr int TNH = TN / 2;
    constexpr int TX = BN / TN;

    __shared__ float As[2][BK][BM + PAD];
    __shared__ float Bs[2][BK][BN + PAD];

    const int tid = threadIdx.x;
    const int bm  = blockIdx.y * BM;
    const int bn  = blockIdx.x * BN;
    const int tx  = tid % TX;
    const int ty  = tid / TX;

    float4 ra[NLA], rb[NLB];
    unsigned long long acc2[TM][TNH];
#pragma unroll
    for (int i = 0; i < TM; i++)
#pragma unroll
        for (int j = 0; j < TNH; j++) acc2[i][j] = 0ull;

    const int KT = K / BK;

    auto prefetch = [&](int kt) {
        int k0 = kt * BK;
#pragma unroll
        for (int l = 0; l < NLA; l++) {
            int i = tid + l * THREADS;
            int rr = i >> 2;
            int kk = k0 + (i & 3) * 4;
            ra[l] = *(const float4*)(A0 + (size_t)(bm + rr) * K + kk);
        }
#pragma unroll
        for (int l = 0; l < NLB; l++) {
            int i = tid + l * THREADS;
            int rr = i >> 2;
            int kk = k0 + (i & 3) * 4;
            rb[l] = *(const float4*)(Bm + (size_t)(bn + rr) * K + kk);
        }
    };
    auto commit = [&](int buf) {
#pragma unroll
        for (int l = 0; l < NLA; l++) {
            int i = tid + l * THREADS;
            int rr = i >> 2;
            int cc = (i & 3) * 4;
            As[buf][cc + 0][rr] = ra[l].x; As[buf][cc + 1][rr] = ra[l].y;
            As[buf][cc + 2][rr] = ra[l].z; As[buf][cc + 3][rr] = ra[l].w;
        }
#pragma unroll
        for (int l = 0; l < NLB; l++) {
            int i = tid + l * THREADS;
            int rr = i >> 2;
            int cc = (i & 3) * 4;
            Bs[buf][cc + 0][rr] = rb[l].x; Bs[buf][cc + 1][rr] = rb[l].y;
            Bs[buf][cc + 2][rr] = rb[l].z; Bs[buf][cc + 3][rr] = rb[l].w;
        }
    };

    prefetch(0);
    commit(0);
    __syncthreads();

    for (int kt = 0; kt < KT; kt++) {
        int buf = kt & 1;
        if (kt + 1 < KT) prefetch(kt + 1);
#pragma unroll
        for (int k = 0; k < BK; k++) {
            float a[TM];
            unsigned long long b2[TNH];
#pragma unroll
            for (int cm = 0; cm < NCHM; cm++) {
                float4 v = *(const float4*)&As[buf][k][cm * (BM / NCHM) + ty * 4];
                a[cm * 4 + 0] = v.x; a[cm * 4 + 1] = v.y;
                a[cm * 4 + 2] = v.z; a[cm * 4 + 3] = v.w;
            }
#pragma unroll
            for (int cn = 0; cn < NCHN; cn++) {
                float4 v = *(const float4*)&Bs[buf][k][cn * (BN / NCHN) + tx * 4];
                b2[cn * 2 + 0] = pk2(v.x, v.y);
                b2[cn * 2 + 1] = pk2(v.z, v.w);
            }
#pragma unroll
            for (int i = 0; i < TM; i++) {
                unsigned long long ad = pk2(a[i], a[i]);
#pragma unroll
                for (int j = 0; j < TNH; j++)
                    fma2(acc2[i][j], ad, b2[j]);
            }
        }
        if (kt + 1 < KT) {
            commit((kt + 1) & 1);
            __syncthreads();
        }
    }

#pragma unroll
    for (int cm = 0; cm < NCHM; cm++) {
#pragma unroll
        for (int jr = 0; jr < 4; jr++) {
            int row = bm + cm * (BM / NCHM) + ty * 4 + jr;
            int i   = cm * 4 + jr;
            float accf[TN];
#pragma unroll
            for (int j = 0; j < TNH; j++)
                upk2(acc2[i][j], accf[2 * j], accf[2 * j + 1]);
#pragma unroll
            for (int cn = 0; cn < NCHN; cn++) {
                int col = bn + cn * (BN / NCHN) + tx * 4;
                *(float4*)(C + (size_t)row * N + col) =
                    make_float4(accf[cn * 4 + 0], accf[cn * 4 + 1],
                                accf[cn * 4 + 2], accf[cn * 4 + 3]);
            }
        }
    }
}

// ---------------- segment-masked causal conv (DCONV=4) + SiLU -------
__global__ __launch_bounds__(256)
void conv_silu(const int* __restrict__ eb,
               const float* __restrict__ cw, const float* __restrict__ cb)
{
    int gi = blockIdx.x * blockDim.x + threadIdx.x;   // over L*512
    int t  = gi >> 9;
    int ch = gi & 511;
    int ebt = eb[t];
    float4 w = *(const float4*)(cw + ch * 4);
    float acc = cb[ch];
    const float wk[4] = {w.x, w.y, w.z, w.w};
#pragma unroll
    for (int k = 0; k < 4; k++) {
        int p = t - 3 + k;
        if (p >= 0 && eb[p] == ebt)
            acc = fmaf(wk[k], g_XZ[p * 1024 + ch], acc);
    }
    float s = acc / (1.f + __expf(-acc));             // SiLU
    g_XC[t * 512 + ch] = s;
}

// ---------------- delta = softplus(dt @ dt_proj_w^T + b) (K=32) -----
__global__ __launch_bounds__(512)
void delta_softplus(const float* __restrict__ w, const float* __restrict__ b)
{
    int ch = threadIdx.x;            // 512 channels
    int t0 = blockIdx.x * 32;
    float wr[32];
#pragma unroll
    for (int r = 0; r < 32; r += 4) {
        float4 v = *(const float4*)(w + ch * 32 + r);
        wr[r] = v.x; wr[r + 1] = v.y; wr[r + 2] = v.z; wr[r + 3] = v.w;
    }
    float bias = b[ch];
    __shared__ float sdt[32][32];
    for (int i = threadIdx.x; i < 32 * 32; i += 512) {
        int tt = i >> 5, r = i & 31;
        sdt[tt][r] = g_DBC[(t0 + tt) * 64 + r];
    }
    __syncthreads();
    for (int tt = 0; tt < 32; tt++) {
        float acc = bias;
#pragma unroll
        for (int r = 0; r < 32; r++) acc = fmaf(sdt[tt][r], wr[r], acc);
        float sp = (acc > 20.f) ? acc : log1pf(expf(acc));
        g_DELTA[(t0 + tt) * 512 + ch] = sp;
    }
}

// ---------------- selective scan: warp = 2 channels x 16 states -----
// 1-deep software prefetch to overlap L2 latency with compute+shfl.
__global__ __launch_bounds__(256)
void scan_kernel(const float* __restrict__ alog, const float* __restrict__ Dv)
{
    int warp = (blockIdx.x << 3) + (threadIdx.x >> 5);  // 0..4095
    int lane = threadIdx.x & 31;
    int pair = warp & 255;                              // 256 channel pairs
    int seg  = warp >> 8;                               // 16 segments
    int ch   = (pair << 1) + (lane >> 4);
    int s    = lane & 15;

    int t0 = g_seg_start[seg];
    if (t0 < 0) return;
    int t1 = g_seg_end[seg];

    float A   = -expf(alog[ch * 16 + s]);
    float Dch = Dv[ch];
    float h = 0.f;

    float delta = g_DELTA[t0 * 512 + ch];
    float xc    = g_XC   [t0 * 512 + ch];
    float Bv    = g_DBC  [t0 * 64 + 32 + s];
    float Cv    = g_DBC  [t0 * 64 + 48 + s];
    float z     = (s == 0) ? g_XZ[t0 * 1024 + 512 + ch] : 0.f;

    for (int t = t0; t < t1; t++) {
        // prefetch next step before the serial chain
        float nd = 0.f, nx = 0.f, nB = 0.f, nC = 0.f, nz = 0.f;
        if (t + 1 < t1) {
            nd = g_DELTA[(t + 1) * 512 + ch];
            nx = g_XC   [(t + 1) * 512 + ch];
            nB = g_DBC  [(t + 1) * 64 + 32 + s];
            nC = g_DBC  [(t + 1) * 64 + 48 + s];
            if (s == 0) nz = g_XZ[(t + 1) * 1024 + 512 + ch];
        }

        float dA = __expf(delta * A);
        h = fmaf(dA, h, delta * Bv * xc);               // reset: h starts at 0
        float v = h * Cv;
        v += __shfl_xor_sync(0xffffffffu, v, 1, 16);
        v += __shfl_xor_sync(0xffffffffu, v, 2, 16);
        v += __shfl_xor_sync(0xffffffffu, v, 4, 16);
        v += __shfl_xor_sync(0xffffffffu, v, 8, 16);
        if (s == 0) {
            float y = fmaf(Dch, xc, v) * (z / (1.f + __expf(-z)));
            __nv_bfloat16 hh, ll;
            split1(y, hh, ll);
            g_Yhi[t * 512 + ch] = hh;
            g_Ylo[t * 512 + ch] = ll;
        }
        delta = nd; xc = nx; Bv = nB; Cv = nC; z = nz;
    }
}

// ---------------- launch -------------------------------------------
extern "C" void kernel_launch(void* const* d_in, const int* in_sizes, int n_in,
                              void* d_out, int out_size)
{
    const float* q    = (const float*)d_in[0];
    const float* kv   = (const float*)d_in[1];
    const float* ke   = (const float*)d_in[2];
    const int*   idx  = (const int*)  d_in[3];
    const int*   eb   = (const int*)  d_in[5];
    const float* ww   = (const float*)d_in[6];
    const float* wb   = (const float*)d_in[7];
    const float* win  = (const float*)d_in[8];
    const float* cw   = (const float*)d_in[9];
    const float* cb   = (const float*)d_in[10];
    const float* xpw  = (const float*)d_in[11];
    const float* dtw  = (const float*)d_in[12];
    const float* dtb  = (const float*)d_in[13];
    const float* alog = (const float*)d_in[14];
    const float* Dv   = (const float*)d_in[15];
    const float* wout = (const float*)d_in[16];
    float* out = (float*)d_out;

    float* pXZ;   cudaGetSymbolAddress((void**)&pXZ,   g_XZ);
    float* pXC;   cudaGetSymbolAddress((void**)&pXC,   g_XC);
    float* pDBC;  cudaGetSymbolAddress((void**)&pDBC,  g_DBC);
    __nv_bfloat16 *pINhi, *pINlo, *pXhi, *pXlo, *pYhi, *pYlo;
    __nv_bfloat16 *pWWi, *pWIi, *pWOi;
    cudaGetSymbolAddress((void**)&pINhi, g_INhi);
    cudaGetSymbolAddress((void**)&pINlo, g_INlo);
    cudaGetSymbolAddress((void**)&pXhi,  g_Xhi);
    cudaGetSymbolAddress((void**)&pXlo,  g_Xlo);
    cudaGetSymbolAddress((void**)&pYhi,  g_Yhi);
    cudaGetSymbolAddress((void**)&pYlo,  g_Ylo);
    cudaGetSymbolAddress((void**)&pWWi,  g_WWi);
    cudaGetSymbolAddress((void**)&pWIi,  g_WIi);
    cudaGetSymbolAddress((void**)&pWOi,  g_WOi);

    cudaFuncSetAttribute(mma_gemm<0>, cudaFuncAttributeMaxDynamicSharedMemorySize, MG_SMEM);
    cudaFuncSetAttribute(mma_gemm<1>, cudaFuncAttributeMaxDynamicSharedMemorySize, MG_SMEM);
    cudaFuncSetAttribute(mma_gemm<2>, cudaFuncAttributeMaxDynamicSharedMemorySize, MG_SMEM);

    // (1) zero output (poisoned by harness)
    cudaMemsetAsync(out, 0, (size_t)out_size * sizeof(float), 0);

    // (2) segment boundaries
    seg_mark<<<1, 256>>>(eb);

    // (3) input hi/lo conversion
    cvt_inputs<<<cL * 3 * cE / 1024, 256>>>(q, kv, ke);

    // (4) Ww conversion (interleaved)
    cvt_w_i<<<cE * 3 * cE / 1024, 256>>>(ww, pWWi, 3 * cE);

    // (5) x = leaky(concat @ Ww^T + b)   M=8192 N=512 K=1536  [profiled launch]
    mma_gemm<0><<<dim3(cE / 128, cL / 128), 256, MG_SMEM>>>(
        pINhi, pINlo, pWWi, wb, nullptr, pXhi, pXlo, nullptr, 3 * cE, cE);

    // (6) Win conversion
    cvt_w_i<<<2 * cD * cE / 1024, 256>>>(win, pWIi, cE);

    // (7) xz = x @ Win^T                 M=8192 N=1024 K=512 -> fp32 XZ
    mma_gemm<1><<<dim3(2 * cD / 128, cL / 128), 256, MG_SMEM>>>(
        pXhi, pXlo, pWIi, nullptr, pXZ, nullptr, nullptr, nullptr, cE, 2 * cD);

    // (8) xc = silu(seg-masked conv(x_in))
    conv_silu<<<cL * cD / 256, 256>>>(eb, cw, cb);

    // (9) dbc = xc @ Wxp^T               M=8192 N=64 K=512
    gemm_nt_small<32, 64, 4, 4><<<dim3(1, cL / 32), 128>>>(
        pXC, xpw, pDBC, cD, 64);

    // (10) delta = softplus(dt @ dtw^T + dtb)
    delta_softplus<<<cL / 32, 512>>>(dtw, dtb);

    // (11) selective scan -> Yhi/Ylo
    scan_kernel<<<512, 256>>>(alog, Dv);

    // (12) Wout conversion
    cvt_w_i<<<cE * cD / 1024, 256>>>(wout, pWOi, cD);

    // (13) out[node] += y @ Wout^T       M=8192 N=512 K=512 + scatter
    mma_gemm<2><<<dim3(cE / 128, cL / 128), 256, MG_SMEM>>>(
        pYhi, pYlo, pWOi, nullptr, out, nullptr, nullptr, idx, cD, cE);
}

// round 17
// speedup vs baseline: 1.1278x; 1.1278x over previous
#include <cuda_runtime.h>
#include <cuda_bf16.h>
#include <cstdint>

// ---------------- problem constants (fixed shapes) ----------------
constexpr int cL  = 8192;   // tokens
constexpr int cE  = 512;    // embed = d
constexpr int cD  = 512;
constexpr int cNG = 16;     // graphs

// ---------------- scratch (device globals; no allocs allowed) ------
__device__ float g_XZ   [cL * 2 * cD];        // 32 MB  [x_in | z]
__device__ float g_XC   [cL * cD];            // 16 MB  silu(conv)
__device__ float g_DBC  [cL * 64];            //  2 MB  [dt(32) | B(16) | C(16)]
__device__ float g_DELTA[cL * cD];            // 16 MB
__device__ int   g_seg_start[cNG];
__device__ int   g_seg_end  [cNG];

// bf16 split operand buffers (planar hi/lo)
__device__ __nv_bfloat16 g_INhi[cL * 3 * cE];   // concat(q,kv,ke)
__device__ __nv_bfloat16 g_INlo[cL * 3 * cE];
__device__ __nv_bfloat16 g_Xhi [cL * cE];       // GEMM1 out (leaky)
__device__ __nv_bfloat16 g_Xlo [cL * cE];
__device__ __nv_bfloat16 g_Yhi [cL * cD];       // scan out
__device__ __nv_bfloat16 g_Ylo [cL * cD];
__device__ __nv_bfloat16 g_WWhi[cE * 3 * cE];
__device__ __nv_bfloat16 g_WWlo[cE * 3 * cE];
__device__ __nv_bfloat16 g_WIhi[2 * cD * cE];
__device__ __nv_bfloat16 g_WIlo[2 * cD * cE];
__device__ __nv_bfloat16 g_WOhi[cE * cD];
__device__ __nv_bfloat16 g_WOlo[cE * cD];

// ---------------- helpers ------------------------------------------
__device__ __forceinline__ uint32_t smem_u32(const void* p) {
    uint32_t a;
    asm("{ .reg .u64 t; cvta.to.shared.u64 t, %1; cvt.u32.u64 %0, t; }"
        : "=r"(a) : "l"(p));
    return a;
}
__device__ __forceinline__ void ldsm4(uint32_t* r, uint32_t addr) {
    asm volatile("ldmatrix.sync.aligned.m8n8.x4.shared.b16 {%0,%1,%2,%3}, [%4];"
                 : "=r"(r[0]), "=r"(r[1]), "=r"(r[2]), "=r"(r[3]) : "r"(addr));
}
__device__ __forceinline__ void mma16816(float* c, const uint32_t* a, const uint32_t* b) {
    asm volatile("mma.sync.aligned.m16n8k16.row.col.f32.bf16.bf16.f32 "
                 "{%0,%1,%2,%3}, {%4,%5,%6,%7}, {%8,%9}, {%0,%1,%2,%3};"
                 : "+f"(c[0]), "+f"(c[1]), "+f"(c[2]), "+f"(c[3])
                 : "r"(a[0]), "r"(a[1]), "r"(a[2]), "r"(a[3]), "r"(b[0]), "r"(b[1]));
}
__device__ __forceinline__ void cp16(uint32_t dst, const void* src) {
    asm volatile("cp.async.cg.shared.global [%0], [%1], 16;"
                 :: "r"(dst), "l"(src) : "memory");
}
__device__ __forceinline__ void cp_commit() {
    asm volatile("cp.async.commit_group;" ::: "memory");
}
template<int N>
__device__ __forceinline__ void cp_wait() {
    asm volatile("cp.async.wait_group %0;" :: "n"(N) : "memory");
}
// split one fp32 into bf16 hi + bf16 lo
__device__ __forceinline__ void split1(float v, __nv_bfloat16& h, __nv_bfloat16& l) {
    h = __float2bfloat16_rn(v);
    l = __float2bfloat16_rn(v - __bfloat162float(h));
}
__device__ __forceinline__ void split4(float4 v, uint2& h, uint2& l) {
    __nv_bfloat16 h0, h1, h2, h3, l0, l1, l2, l3;
    split1(v.x, h0, l0); split1(v.y, h1, l1);
    split1(v.z, h2, l2); split1(v.w, h3, l3);
    __nv_bfloat162 H01{h0, h1}, H23{h2, h3}, L01{l0, l1}, L23{l2, l3};
    h.x = *(uint32_t*)&H01; h.y = *(uint32_t*)&H23;
    l.x = *(uint32_t*)&L01; l.y = *(uint32_t*)&L23;
}

// ---------------- packed fp32x2 (small GEMM) -----------------------
__device__ __forceinline__ unsigned long long pk2(float lo, float hi) {
    unsigned long long r;
    asm("mov.b64 %0, {%1, %2};" : "=l"(r) : "f"(lo), "f"(hi));
    return r;
}
__device__ __forceinline__ void fma2(unsigned long long& d,
                                     unsigned long long a, unsigned long long b) {
    asm("fma.rn.f32x2 %0, %1, %2, %0;" : "+l"(d) : "l"(a), "l"(b));
}
__device__ __forceinline__ void upk2(unsigned long long v, float& lo, float& hi) {
    asm("mov.b64 {%0, %1}, %2;" : "=f"(lo), "=f"(hi) : "l"(v));
}

// ---------------- conversion prepasses -----------------------------
__global__ __launch_bounds__(256)
void cvt_inputs(const float* __restrict__ q, const float* __restrict__ kv,
                const float* __restrict__ ke)
{
    int i = blockIdx.x * 256 + threadIdx.x;       // one per 4 elems
    int e = i * 4;
    int row = e / 1536;
    int col = e - row * 1536;
    const float* base = (col < 512) ? q : ((col < 1024) ? kv : ke);
    float4 v = *(const float4*)(base + (size_t)row * 512 + (col & 511));
    uint2 h, l;
    split4(v, h, l);
    *(uint2*)(g_INhi + e) = h;
    *(uint2*)(g_INlo + e) = l;
}

__global__ __launch_bounds__(256)
void cvt_w(const float* __restrict__ src, __nv_bfloat16* __restrict__ hi,
           __nv_bfloat16* __restrict__ lo)
{
    int e = (blockIdx.x * 256 + threadIdx.x) * 4;
    float4 v = *(const float4*)(src + e);
    uint2 h, l;
    split4(v, h, l);
    *(uint2*)(hi + e) = h;
    *(uint2*)(lo + e) = l;
}

// ---------------- segment boundary extraction ----------------------
__global__ void seg_mark(const int* __restrict__ eb) {
    int tid = threadIdx.x;
    if (tid < cNG) { g_seg_start[tid] = -1; g_seg_end[tid] = -1; }
    __syncthreads();
    for (int t = tid; t < cL; t += blockDim.x) {
        int g = eb[t];
        if (t == 0      || eb[t - 1] != g) g_seg_start[g] = t;
        if (t == cL - 1 || eb[t + 1] != g) g_seg_end[g]   = t + 1;
    }
}

// =====================================================================
// HMMA split-bf16 NT GEMM with cp.async 2-stage pipeline.
// C[M,N] = A*B^T, A,B bf16 hi/lo; terms hi*hi + hi*lo + lo*hi, fp32 acc.
// Tile 128x128, BK=32. 4 warps of 64x64 (square warp tile minimizes
// smem crossbar traffic: LDSM A 32KB + B 32KB + STS 32KB per chunk).
// 128 threads, 2 CTAs/SM, 256-reg budget -> no spills with acc[4][8][4].
// MODE 0: bias + leaky -> bf16 hi/lo out ; MODE 1: fp32 store ;
// MODE 2: atomicAdd into C[idx[row]*N + col]
// =====================================================================
constexpr int TSTR = 40;                 // smem row stride (bf16 elems)
constexpr int TSZ  = 128 * TSTR;         // one plane (5120 elems, 10 KB)
constexpr int STG  = 4 * TSZ;            // stage: AH|AL|BH|BL (40 KB)
constexpr int MG_SMEM = 2 * STG * 2;     // bytes: 2 stages = 81920

template<int MODE>
__global__ __launch_bounds__(128, 2)
void mma_gemm(const __nv_bfloat16* __restrict__ Ahi, const __nv_bfloat16* __restrict__ Alo,
              const __nv_bfloat16* __restrict__ Bhi, const __nv_bfloat16* __restrict__ Blo,
              const float* __restrict__ bias, float* __restrict__ C,
              __nv_bfloat16* __restrict__ Ohi, __nv_bfloat16* __restrict__ Olo,
              const int* __restrict__ idx, int K, int N)
{
    extern __shared__ __nv_bfloat16 smd[];
    const int tid  = threadIdx.x;
    const int wid  = tid >> 5;
    const int lane = tid & 31;
    const int wm   = wid & 1;                 // 2 warp-rows (64 each)
    const int wn   = wid >> 1;                // 2 warp-cols (64 each)
    const int bm   = blockIdx.y * 128;
    const int bn   = blockIdx.x * 128;

    float acc[4][8][4];
#pragma unroll
    for (int i = 0; i < 4; i++)
#pragma unroll
        for (int j = 0; j < 8; j++)
#pragma unroll
            for (int k = 0; k < 4; k++) acc[i][j][k] = 0.f;

    const uint32_t sb = smem_u32(smd);
    const int KT = K / 32;

    const __nv_bfloat16* bases[4] = {
        Ahi + (size_t)bm * K, Alo + (size_t)bm * K,
        Bhi + (size_t)bn * K, Blo + (size_t)bn * K };

    auto issue = [&](int c) {
        const int st = c & 1;
        const int kb = c * 32;
#pragma unroll
        for (int i = 0; i < 16; i++) {
            int g  = tid + 128 * i;        // 0..2047
            int t  = g >> 9;               // plane AH/AL/BH/BL
            int gg = g & 511;
            int row = gg >> 2, u = gg & 3;
            uint32_t dst = sb + 2 * (st * STG + t * TSZ + row * TSTR + u * 8);
            cp16(dst, bases[t] + (size_t)row * K + kb + u * 8);
        }
        cp_commit();
    };

    issue(0);

    // ldsm4 B packing: lanes 0-7 ->(nf,k0) 8-15 ->(nf,k8) 16-23 ->(nf+1,k0) 24-31 ->(nf+1,k8)
    const int bquad = lane >> 3;
    const int brr   = lane & 7;

    for (int c = 0; c < KT; c++) {
        if (c + 1 < KT) { issue(c + 1); cp_wait<1>(); }
        else            { cp_wait<0>(); }
        __syncthreads();

        const uint32_t stb = sb + 2 * ((c & 1) * STG);

#pragma unroll
        for (int ks = 0; ks < 2; ks++) {
            // ---- B fragments: 8 nf-slots via 4+4 ldsm4 --------------
            uint32_t bh[8][2], bl[8][2];
            const uint32_t brow = wn * 64 + (bquad >> 1) * 8 + brr;
            const uint32_t bcol = ks * 16 + (bquad & 1) * 8;
#pragma unroll
            for (int nf2 = 0; nf2 < 4; nf2++) {
                uint32_t off = (brow + nf2 * 16) * TSTR + bcol;
                uint32_t r[4];
                ldsm4(r, stb + 2 * (2 * TSZ + off));
                bh[2 * nf2][0] = r[0]; bh[2 * nf2][1] = r[1];
                bh[2 * nf2 + 1][0] = r[2]; bh[2 * nf2 + 1][1] = r[3];
                ldsm4(r, stb + 2 * (3 * TSZ + off));
                bl[2 * nf2][0] = r[0]; bl[2 * nf2][1] = r[1];
                bl[2 * nf2 + 1][0] = r[2]; bl[2 * nf2 + 1][1] = r[3];
            }
            // ---- A fragments per-mf, 3-term MMAs --------------------
            const uint32_t arow = wm * 64 + (lane & 15);
            const uint32_t acol = ks * 16 + (lane >> 4) * 8;
#pragma unroll
            for (int mf = 0; mf < 4; mf++) {
                uint32_t ah[4], al[4];
                uint32_t off = (arow + mf * 16) * TSTR + acol;
                ldsm4(ah, stb + 2 * off);
                ldsm4(al, stb + 2 * (TSZ + off));
#pragma unroll
                for (int nf = 0; nf < 8; nf++) {
                    mma16816(acc[mf][nf], ah, bh[nf]);
                    mma16816(acc[mf][nf], ah, bl[nf]);
                    mma16816(acc[mf][nf], al, bh[nf]);
                }
            }
        }
        __syncthreads();
    }

    // ---------------- epilogue ----------------
    const int r  = lane >> 2;
    const int cp = (lane & 3) * 2;
#pragma unroll
    for (int mf = 0; mf < 4; mf++) {
#pragma unroll
        for (int half = 0; half < 2; half++) {
            const int m = bm + wm * 64 + mf * 16 + r + half * 8;
            int node = 0;
            if constexpr (MODE == 2) node = idx[m];
#pragma unroll
            for (int nf = 0; nf < 8; nf++) {
                const int n = bn + wn * 64 + nf * 8 + cp;
                float v0 = acc[mf][nf][half * 2 + 0];
                float v1 = acc[mf][nf][half * 2 + 1];
                if constexpr (MODE == 0) {
                    float2 bv = *(const float2*)(bias + n);
                    v0 += bv.x; v1 += bv.y;
                    v0 = (v0 >= 0.f) ? v0 : 0.01f * v0;
                    v1 = (v1 >= 0.f) ? v1 : 0.01f * v1;
                    __nv_bfloat16 h0, h1, l0, l1;
                    split1(v0, h0, l0); split1(v1, h1, l1);
                    __nv_bfloat162 H{h0, h1}, L{l0, l1};
                    *(__nv_bfloat162*)(Ohi + (size_t)m * N + n) = H;
                    *(__nv_bfloat162*)(Olo + (size_t)m * N + n) = L;
                } else if constexpr (MODE == 1) {
                    *(float2*)(C + (size_t)m * N + n) = make_float2(v0, v1);
                } else {
                    float* p = C + (size_t)node * N + n;
                    atomicAdd(p + 0, v0);
                    atomicAdd(p + 1, v1);
                }
            }
        }
    }
}

// ---------------- small FFMA2 NT GEMM (dbc, N=64) -------------------
template<int BM, int BN, int TM, int TN>
__global__ __launch_bounds__((BM / TM) * (BN / TN))
void gemm_nt_small(const float* __restrict__ A0, const float* __restrict__ Bm,
                   float* __restrict__ C, int K, int N)
{
    constexpr int THREADS = (BM / TM) * (BN / TN);
    constexpr int BK  = 16;
    constexpr int NLA = (BM * BK / 4) / THREADS;
    constexpr int NLB = (BN * BK / 4) / THREADS;
    constexpr int PAD = 4;
    constexpr int NCHM = TM / 4, NCHN = TN / 4;
    constexpr int TNH = TN / 2;
    constexpr int TX = BN / TN;

    __shared__ float As[2][BK][BM + PAD];
    __shared__ float Bs[2][BK][BN + PAD];

    const int tid = threadIdx.x;
    const int bm  = blockIdx.y * BM;
    const int bn  = blockIdx.x * BN;
    const int tx  = tid % TX;
    const int ty  = tid / TX;

    float4 ra[NLA], rb[NLB];
    unsigned long long acc2[TM][TNH];
#pragma unroll
    for (int i = 0; i < TM; i++)
#pragma unroll
        for (int j = 0; j < TNH; j++) acc2[i][j] = 0ull;

    const int KT = K / BK;

    auto prefetch = [&](int kt) {
        int k0 = kt * BK;
#pragma unroll
        for (int l = 0; l < NLA; l++) {
            int i = tid + l * THREADS;
            int rr = i >> 2;
            int kk = k0 + (i & 3) * 4;
            ra[l] = *(const float4*)(A0 + (size_t)(bm + rr) * K + kk);
        }
#pragma unroll
        for (int l = 0; l < NLB; l++) {
            int i = tid + l * THREADS;
            int rr = i >> 2;
            int kk = k0 + (i & 3) * 4;
            rb[l] = *(const float4*)(Bm + (size_t)(bn + rr) * K + kk);
        }
    };
    auto commit = [&](int buf) {
#pragma unroll
        for (int l = 0; l < NLA; l++) {
            int i = tid + l * THREADS;
            int rr = i >> 2;
            int cc = (i & 3) * 4;
            As[buf][cc + 0][rr] = ra[l].x; As[buf][cc + 1][rr] = ra[l].y;
            As[buf][cc + 2][rr] = ra[l].z; As[buf][cc + 3][rr] = ra[l].w;
        }
#pragma unroll
        for (int l = 0; l < NLB; l++) {
            int i = tid + l * THREADS;
            int rr = i >> 2;
            int cc = (i & 3) * 4;
            Bs[buf][cc + 0][rr] = rb[l].x; Bs[buf][cc + 1][rr] = rb[l].y;
            Bs[buf][cc + 2][rr] = rb[l].z; Bs[buf][cc + 3][rr] = rb[l].w;
        }
    };

    prefetch(0);
    commit(0);
    __syncthreads();

    for (int kt = 0; kt < KT; kt++) {
        int buf = kt & 1;
        if (kt + 1 < KT) prefetch(kt + 1);
#pragma unroll
        for (int k = 0; k < BK; k++) {
            float a[TM];
            unsigned long long b2[TNH];
#pragma unroll
            for (int cm = 0; cm < NCHM; cm++) {
                float4 v = *(const float4*)&As[buf][k][cm * (BM / NCHM) + ty * 4];
                a[cm * 4 + 0] = v.x; a[cm * 4 + 1] = v.y;
                a[cm * 4 + 2] = v.z; a[cm * 4 + 3] = v.w;
            }
#pragma unroll
            for (int cn = 0; cn < NCHN; cn++) {
                float4 v = *(const float4*)&Bs[buf][k][cn * (BN / NCHN) + tx * 4];
                b2[cn * 2 + 0] = pk2(v.x, v.y);
                b2[cn * 2 + 1] = pk2(v.z, v.w);
            }
#pragma unroll
            for (int i = 0; i < TM; i++) {
                unsigned long long ad = pk2(a[i], a[i]);
#pragma unroll
                for (int j = 0; j < TNH; j++)
                    fma2(acc2[i][j], ad, b2[j]);
            }
        }
        if (kt + 1 < KT) {
            commit((kt + 1) & 1);
            __syncthreads();
        }
    }

#pragma unroll
    for (int cm = 0; cm < NCHM; cm++) {
#pragma unroll
        for (int jr = 0; jr < 4; jr++) {
            int row = bm + cm * (BM / NCHM) + ty * 4 + jr;
            int i   = cm * 4 + jr;
            float accf[TN];
#pragma unroll
            for (int j = 0; j < TNH; j++)
                upk2(acc2[i][j], accf[2 * j], accf[2 * j + 1]);
#pragma unroll
            for (int cn = 0; cn < NCHN; cn++) {
                int col = bn + cn * (BN / NCHN) + tx * 4;
                *(float4*)(C + (size_t)row * N + col) =
                    make_float4(accf[cn * 4 + 0], accf[cn * 4 + 1],
                                accf[cn * 4 + 2], accf[cn * 4 + 3]);
            }
        }
    }
}

// ---------------- segment-masked causal conv (DCONV=4) + SiLU -------
__global__ __launch_bounds__(256)
void conv_silu(const int* __restrict__ eb,
               const float* __restrict__ cw, const float* __restrict__ cb)
{
    int gi = blockIdx.x * blockDim.x + threadIdx.x;   // over L*512
    int t  = gi >> 9;
    int ch = gi & 511;
    int ebt = eb[t];
    float4 w = *(const float4*)(cw + ch * 4);
    float acc = cb[ch];
    const float wk[4] = {w.x, w.y, w.z, w.w};
#pragma unroll
    for (int k = 0; k < 4; k++) {
        int p = t - 3 + k;
        if (p >= 0 && eb[p] == ebt)
            acc = fmaf(wk[k], g_XZ[p * 1024 + ch], acc);
    }
    float s = acc / (1.f + __expf(-acc));             // SiLU
    g_XC[t * 512 + ch] = s;
}

// ---------------- delta = softplus(dt @ dt_proj_w^T + b) (K=32) -----
__global__ __launch_bounds__(512)
void delta_softplus(const float* __restrict__ w, const float* __restrict__ b)
{
    int ch = threadIdx.x;            // 512 channels
    int t0 = blockIdx.x * 32;
    float wr[32];
#pragma unroll
    for (int r = 0; r < 32; r += 4) {
        float4 v = *(const float4*)(w + ch * 32 + r);
        wr[r] = v.x; wr[r + 1] = v.y; wr[r + 2] = v.z; wr[r + 3] = v.w;
    }
    float bias = b[ch];
    __shared__ float sdt[32][32];
    for (int i = threadIdx.x; i < 32 * 32; i += 512) {
        int tt = i >> 5, r = i & 31;
        sdt[tt][r] = g_DBC[(t0 + tt) * 64 + r];
    }
    __syncthreads();
    for (int tt = 0; tt < 32; tt++) {
        float acc = bias;
#pragma unroll
        for (int r = 0; r < 32; r++) acc = fmaf(sdt[tt][r], wr[r], acc);
        float sp = (acc > 20.f) ? acc : log1pf(expf(acc));
        g_DELTA[(t0 + tt) * 512 + ch] = sp;
    }
}

// ---------------- selective scan: warp = 2 channels x 16 states -----
// 1-deep software prefetch to overlap L2 latency with compute+shfl.
__global__ __launch_bounds__(256)
void scan_kernel(const float* __restrict__ alog, const float* __restrict__ Dv)
{
    int warp = (blockIdx.x << 3) + (threadIdx.x >> 5);  // 0..4095
    int lane = threadIdx.x & 31;
    int pair = warp & 255;                              // 256 channel pairs
    int seg  = warp >> 8;                               // 16 segments
    int ch   = (pair << 1) + (lane >> 4);
    int s    = lane & 15;

    int t0 = g_seg_start[seg];
    if (t0 < 0) return;
    int t1 = g_seg_end[seg];

    float A   = -expf(alog[ch * 16 + s]);
    float Dch = Dv[ch];
    float h = 0.f;

    float delta = g_DELTA[t0 * 512 + ch];
    float xc    = g_XC   [t0 * 512 + ch];
    float Bv    = g_DBC  [t0 * 64 + 32 + s];
    float Cv    = g_DBC  [t0 * 64 + 48 + s];
    float z     = (s == 0) ? g_XZ[t0 * 1024 + 512 + ch] : 0.f;

    for (int t = t0; t < t1; t++) {
        // prefetch next step before the serial chain
        float nd = 0.f, nx = 0.f, nB = 0.f, nC = 0.f, nz = 0.f;
        if (t + 1 < t1) {
            nd = g_DELTA[(t + 1) * 512 + ch];
            nx = g_XC   [(t + 1) * 512 + ch];
            nB = g_DBC  [(t + 1) * 64 + 32 + s];
            nC = g_DBC  [(t + 1) * 64 + 48 + s];
            if (s == 0) nz = g_XZ[(t + 1) * 1024 + 512 + ch];
        }

        float dA = __expf(delta * A);
        h = fmaf(dA, h, delta * Bv * xc);               // reset: h starts at 0
        float v = h * Cv;
        v += __shfl_xor_sync(0xffffffffu, v, 1, 16);
        v += __shfl_xor_sync(0xffffffffu, v, 2, 16);
        v += __shfl_xor_sync(0xffffffffu, v, 4, 16);
        v += __shfl_xor_sync(0xffffffffu, v, 8, 16);
        if (s == 0) {
            float y = fmaf(Dch, xc, v) * (z / (1.f + __expf(-z)));
            __nv_bfloat16 hh, ll;
            split1(y, hh, ll);
            g_Yhi[t * 512 + ch] = hh;
            g_Ylo[t * 512 + ch] = ll;
        }
        delta = nd; xc = nx; Bv = nB; Cv = nC; z = nz;
    }
}

// ---------------- launch -------------------------------------------
extern "C" void kernel_launch(void* const* d_in, const int* in_sizes, int n_in,
                              void* d_out, int out_size)
{
    const float* q    = (const float*)d_in[0];
    const float* kv   = (const float*)d_in[1];
    const float* ke   = (const float*)d_in[2];
    const int*   idx  = (const int*)  d_in[3];
    const int*   eb   = (const int*)  d_in[5];
    const float* ww   = (const float*)d_in[6];
    const float* wb   = (const float*)d_in[7];
    const float* win  = (const float*)d_in[8];
    const float* cw   = (const float*)d_in[9];
    const float* cb   = (const float*)d_in[10];
    const float* xpw  = (const float*)d_in[11];
    const float* dtw  = (const float*)d_in[12];
    const float* dtb  = (const float*)d_in[13];
    const float* alog = (const float*)d_in[14];
    const float* Dv   = (const float*)d_in[15];
    const float* wout = (const float*)d_in[16];
    float* out = (float*)d_out;

    float* pXZ;   cudaGetSymbolAddress((void**)&pXZ,   g_XZ);
    float* pXC;   cudaGetSymbolAddress((void**)&pXC,   g_XC);
    float* pDBC;  cudaGetSymbolAddress((void**)&pDBC,  g_DBC);
    __nv_bfloat16 *pINhi, *pINlo, *pXhi, *pXlo, *pYhi, *pYlo;
    __nv_bfloat16 *pWWhi, *pWWlo, *pWIhi, *pWIlo, *pWOhi, *pWOlo;
    cudaGetSymbolAddress((void**)&pINhi, g_INhi);
    cudaGetSymbolAddress((void**)&pINlo, g_INlo);
    cudaGetSymbolAddress((void**)&pXhi,  g_Xhi);
    cudaGetSymbolAddress((void**)&pXlo,  g_Xlo);
    cudaGetSymbolAddress((void**)&pYhi,  g_Yhi);
    cudaGetSymbolAddress((void**)&pYlo,  g_Ylo);
    cudaGetSymbolAddress((void**)&pWWhi, g_WWhi);
    cudaGetSymbolAddress((void**)&pWWlo, g_WWlo);
    cudaGetSymbolAddress((void**)&pWIhi, g_WIhi);
    cudaGetSymbolAddress((void**)&pWIlo, g_WIlo);
    cudaGetSymbolAddress((void**)&pWOhi, g_WOhi);
    cudaGetSymbolAddress((void**)&pWOlo, g_WOlo);

    cudaFuncSetAttribute(mma_gemm<0>, cudaFuncAttributeMaxDynamicSharedMemorySize, MG_SMEM);
    cudaFuncSetAttribute(mma_gemm<1>, cudaFuncAttributeMaxDynamicSharedMemorySize, MG_SMEM);
    cudaFuncSetAttribute(mma_gemm<2>, cudaFuncAttributeMaxDynamicSharedMemorySize, MG_SMEM);

    // (1) zero output (poisoned by harness)
    cudaMemsetAsync(out, 0, (size_t)out_size * sizeof(float), 0);

    // (2) segment boundaries
    seg_mark<<<1, 256>>>(eb);

    // (3) input hi/lo conversion
    cvt_inputs<<<cL * 3 * cE / 1024, 256>>>(q, kv, ke);

    // (4) Ww conversion
    cvt_w<<<cE * 3 * cE / 1024, 256>>>(ww, pWWhi, pWWlo);

    // (5) x = leaky(concat @ Ww^T + b)   M=8192 N=512 K=1536  [profiled launch]
    mma_gemm<0><<<dim3(cE / 128, cL / 128), 128, MG_SMEM>>>(
        pINhi, pINlo, pWWhi, pWWlo, wb, nullptr, pXhi, pXlo, nullptr, 3 * cE, cE);

    // (6) Win conversion
    cvt_w<<<2 * cD * cE / 1024, 256>>>(win, pWIhi, pWIlo);

    // (7) xz = x @ Win^T                 M=8192 N=1024 K=512 -> fp32 XZ
    mma_gemm<1><<<dim3(2 * cD / 128, cL / 128), 128, MG_SMEM>>>(
        pXhi, pXlo, pWIhi, pWIlo, nullptr, pXZ, nullptr, nullptr, nullptr, cE, 2 * cD);

    // (8) xc = silu(seg-masked conv(x_in))
    conv_silu<<<cL * cD / 256, 256>>>(eb, cw, cb);

    // (9) dbc = xc @ Wxp^T               M=8192 N=64 K=512
    gemm_nt_small<32, 64, 4, 4><<<dim3(1, cL / 32), 128>>>(
        pXC, xpw, pDBC, cD, 64);

    // (10) delta = softplus(dt @ dtw^T + dtb)
    delta_softplus<<<cL / 32, 512>>>(dtw, dtb);

    // (11) selective scan -> Yhi/Ylo
    scan_kernel<<<512, 256>>>(alog, Dv);

    // (12) Wout conversion
    cvt_w<<<cE * cD / 1024, 256>>>(wout, pWOhi, pWOlo);

    // (13) out[node] += y @ Wout^T       M=8192 N=512 K=512 + scatter
    mma_gemm<2><<<dim3(cE / 128, cL / 128), 128, MG_SMEM>>>(
        pYhi, pYlo, pWOhi, pWOlo, nullptr, out, nullptr, nullptr, idx, cD, cE);
}